// round 5
// baseline (speedup 1.0000x reference)
#include <cuda_runtime.h>
#include <math.h>

#define Bb 4
#define Nn 32
#define Mm 64
#define Kk 16
#define K1 17
#define Pp 128
#define Ww 128
#define TWd 256

typedef unsigned long long ull;

// ---------- f32x2 helpers ----------
__device__ __forceinline__ ull pack2(float a, float b) {
    ull r; asm("mov.b64 %0, {%1, %2};" : "=l"(r) : "f"(a), "f"(b)); return r;
}
__device__ __forceinline__ void unpack2(ull v, float& a, float& b) {
    asm("mov.b64 {%0, %1}, %2;" : "=f"(a), "=f"(b) : "l"(v));
}
__device__ __forceinline__ void fma2(ull& d, ull a, ull b) {
    asm("fma.rn.f32x2 %0, %1, %2, %0;" : "+l"(d) : "l"(a), "l"(b));
}
__device__ __forceinline__ ull add2(ull a, ull b) {
    ull r; asm("add.rn.f32x2 %0, %1, %2;" : "=l"(r) : "l"(a), "l"(b)); return r;
}
// exact identity tanh = 1 - 2/(exp(2x)+1); only error is __expf rounding (~2^-21)
__device__ __forceinline__ float ftanh(float x) {
    float e = __expf(2.0f * x);
    return 1.0f - __fdividef(2.0f, e + 1.0f);
}

// ------- scratch (device globals; no runtime allocation) -------
__device__ float d_A[Bb*Nn*K1*TWd];
__device__ float d_Bm[Bb*Mm*TWd];
__device__ float d_gdot[Bb*Nn*Mm];
__device__ float d_sw0T[Ww*Ww];   // [w][i]
__device__ float d_sw1T[Ww*Ww];   // [w][i]

// =====================================================================
// K_tr: transpose sw0/sw1 for coalesced column access
// =====================================================================
__global__ void k_tr(const float* __restrict__ sw0, const float* __restrict__ sw1)
{
    const int idx = blockIdx.x*256 + threadIdx.x;  // 0..16383
    const int i = idx >> 7, w = idx & 127;
    d_sw0T[w*Ww + i] = sw0[idx];
    d_sw1T[w*Ww + i] = sw1[idx];
}

// =====================================================================
// K1: attention MLP + softmax + coeff + A-partial.  One block per (b,n,k1).
// =====================================================================
__global__ void __launch_bounds__(128) k1_attn(
    const float* __restrict__ phase, const float* __restrict__ posc,
    const float* __restrict__ sigma, const float* __restrict__ velc,
    const float* __restrict__ aw0, const float* __restrict__ ab0,
    const float* __restrict__ aw1, const float* __restrict__ ab1,
    const float* __restrict__ aw2, const float* __restrict__ ab2,
    const float* __restrict__ tw0, const float* __restrict__ tb0)
{
    __shared__ float s_aw0[6*64];
    __shared__ float s_ab0[64];
    __shared__ float s_aw1[64*64];
    __shared__ float s_ab1[64];
    __shared__ float s_aw2[64];
    __shared__ float red[128];

    const int bx = blockIdx.x;
    const int k1 = bx % K1;
    const int n  = (bx / K1) % Nn;
    const int b  = bx / (K1*Nn);
    const int t  = threadIdx.x;

    for (int i = t; i < 6*64; i += 128) s_aw0[i] = aw0[i];
    if (t < 64) { s_ab0[t] = ab0[t]; s_aw2[t] = aw2[t]; s_ab1[t] = ab1[t]; }
    for (int i = t; i < 64*64; i += 128) s_aw1[i] = aw1[i];
    __syncthreads();

    const float x0 = phase[(b*Nn+n)*4 + 0];
    const float x1 = phase[(b*Nn+n)*4 + 1];
    float va0, va1;
    if (k1 == 0) { va0 = phase[(b*Nn+n)*4 + 2]; va1 = phase[(b*Nn+n)*4 + 3]; }
    else         { va0 = velc[(b*Kk + (k1-1))*2 + 0]; va1 = velc[(b*Kk + (k1-1))*2 + 1]; }
    const float inv = rsqrtf(va0*va0 + va1*va1 + 1e-16f);
    const float ag0 = va0*inv, ag1 = va1*inv;

    const float rx = x0 - posc[(b*Pp + t)*2 + 0];
    const float ry = x1 - posc[(b*Pp + t)*2 + 1];
    const float rd = sqrtf(rx*rx + ry*ry + 1e-16f);
    const float pl = rx*ag0 + ry*ag1;
    const float al = pl / (rd + 1e-8f);

    float h0[64];
#pragma unroll
    for (int j = 0; j < 64; j++) {
        h0[j] = ftanh(s_ab0[j] + x0*s_aw0[0*64+j] + x1*s_aw0[1*64+j]
                              + va0*s_aw0[2*64+j] + va1*s_aw0[3*64+j]
                              + al*s_aw0[4*64+j] + pl*s_aw0[5*64+j]);
    }
    float logit = ab2[0];
#pragma unroll
    for (int g = 0; g < 4; g++) {
        ull acc[8];
#pragma unroll
        for (int p = 0; p < 8; p++) acc[p] = 0ull;
        for (int j = 0; j < 64; j++) {
            const ull hp = pack2(h0[j], h0[j]);
            const float* wrow = &s_aw1[j*64 + g*16];
            ulonglong2 wA = *reinterpret_cast<const ulonglong2*>(wrow + 0);
            ulonglong2 wB = *reinterpret_cast<const ulonglong2*>(wrow + 4);
            ulonglong2 wC = *reinterpret_cast<const ulonglong2*>(wrow + 8);
            ulonglong2 wD = *reinterpret_cast<const ulonglong2*>(wrow + 12);
            fma2(acc[0], hp, wA.x); fma2(acc[1], hp, wA.y);
            fma2(acc[2], hp, wB.x); fma2(acc[3], hp, wB.y);
            fma2(acc[4], hp, wC.x); fma2(acc[5], hp, wC.y);
            fma2(acc[6], hp, wD.x); fma2(acc[7], hp, wD.y);
        }
#pragma unroll
        for (int p = 0; p < 8; p++) {
            const int i = g*16 + p*2;
            float a0, a1; unpack2(acc[p], a0, a1);
            logit += ftanh(a0 + s_ab1[i])   * s_aw2[i]
                   + ftanh(a1 + s_ab1[i+1]) * s_aw2[i+1];
        }
    }

    float lg = (pl > 0.0f) ? logit : -1e30f;
    red[t] = lg; __syncthreads();
    for (int s = 64; s > 0; s >>= 1) { if (t < s) red[t] = fmaxf(red[t], red[t+s]); __syncthreads(); }
    const float mx = red[0]; __syncthreads();
    const float e = __expf(lg - mx);
    red[t] = e; __syncthreads();
    for (int s = 64; s > 0; s >>= 1) { if (t < s) red[t] += red[t+s]; __syncthreads(); }
    const float denom = red[0]; __syncthreads();
    const float aw = e / denom;

    const float sg0 = sigma[(b*Pp+t)*2 + 0];
    const float sg1 = sigma[(b*Pp+t)*2 + 1];
    red[t] = aw*sg0; __syncthreads();
    for (int s = 64; s > 0; s >>= 1) { if (t < s) red[t] += red[t+s]; __syncthreads(); }
    const float sum0 = red[0]; __syncthreads();
    red[t] = aw*sg1; __syncthreads();
    for (int s = 64; s > 0; s >>= 1) { if (t < s) red[t] += red[t+s]; __syncthreads(); }
    const float sum1 = red[0]; __syncthreads();

    const float c0 = __expf(-sum0);
    const float c1 = __expf(-sum1);

    for (int tt = t; tt < TWd; tt += 128) {
        float a = tb0[tt]
                + x0*tw0[0*TWd+tt] + x1*tw0[1*TWd+tt]
                + va0*tw0[2*TWd+tt] + va1*tw0[3*TWd+tt]
                + c0*tw0[8*TWd+tt] + c1*tw0[9*TWd+tt];
        d_A[bx*TWd + tt] = a;
    }
}

// =====================================================================
__global__ void k_bm(const float* __restrict__ bcoords, const float* __restrict__ tw0)
{
    const int bm = blockIdx.x;
    const int t  = threadIdx.x;
    const float xp0 = bcoords[bm*4+0], xp1 = bcoords[bm*4+1];
    const float vp0 = bcoords[bm*4+2], vp1 = bcoords[bm*4+3];
    d_Bm[bm*TWd + t] = xp0*tw0[4*TWd+t] + xp1*tw0[5*TWd+t]
                     + vp0*tw0[6*TWd+t] + vp1*tw0[7*TWd+t];
}

// =====================================================================
// K4: transport MLP + scattering chain. One block per (b,n,m-pair),
// 64 THREADS. m's in f32x2 lanes. Layer1: 4 cols/thread (68 f32x2 accs) ->
// 34 LDS + 16 LDG per 272 fma2 instrs: FMA-pipe bound, not L1 bound.
// =====================================================================
__global__ void __launch_bounds__(64, 5) k4_main(
    const float* __restrict__ scat, const float* __restrict__ sscat,
    const float* __restrict__ vwt,
    const float* __restrict__ tw1, const float* __restrict__ tb1,
    const float* __restrict__ tw2, const float* __restrict__ tb2,
    const float* __restrict__ sb0, const float* __restrict__ sb1,
    const float* __restrict__ out_w)
{
    __shared__ float buf[8704];      // h0(17x512) -> h1(17x512) -> [g(17x256)|rr(17x256)]
    __shared__ ull   ws2[272];
    __shared__ float sres[256];
    __shared__ float sred[8];

    const int bx   = blockIdx.x;
    const int pair = bx & 31;
    const int n    = (bx >> 5) & 31;
    const int b    = bx >> 10;
    const int t    = threadIdx.x;    // 0..63

    for (int i = t; i < 272; i += 64) {
        const int row = i >> 4, j = i & 15;
        float v = (row == 0) ? (1.0f - scat[(b*Nn+n)*Kk + j])
                             : (1.0f - sscat[b*256 + (row-1)*Kk + j]);
        v *= vwt[b*Kk + j];
        ws2[i] = pack2(v, v);
    }

    // ---- layer 0: h0 pairs, 4 positions per thread ----
    const float* Arow = d_A + (b*Nn + n)*K1*TWd;
    const float* bm0  = d_Bm + (b*Mm + pair*2 + 0)*TWd;
    const float* bm1  = bm0 + TWd;
    {
        float bv0[4], bv1[4];
#pragma unroll
        for (int o = 0; o < 4; o++) { bv0[o] = bm0[t + 64*o]; bv1[o] = bm1[t + 64*o]; }
#pragma unroll
        for (int k = 0; k < K1; k++) {
#pragma unroll
            for (int o = 0; o < 4; o++) {
                const float A = Arow[k*TWd + t + 64*o];
                *reinterpret_cast<ull*>(buf + k*512 + 2*(t + 64*o)) =
                    pack2(ftanh(A + bv0[o]), ftanh(A + bv1[o]));
            }
        }
    }
    __syncthreads();

    // ---- layer 1: h1 = tanh(h0 @ tw1 + tb1); thread owns 4 columns ----
    {
        ull a0[K1], a1[K1], a2[K1], a3[K1];
#pragma unroll
        for (int k = 0; k < K1; k++) { a0[k]=0ull; a1[k]=0ull; a2[k]=0ull; a3[k]=0ull; }
        for (int j = 0; j < TWd; j += 4) {
            const float* w = tw1 + j*TWd + t;
            ull pw[4][4];
#pragma unroll
            for (int jj = 0; jj < 4; jj++) {
#pragma unroll
                for (int c = 0; c < 4; c++) {
                    const float wv = w[jj*TWd + 64*c];
                    pw[c][jj] = pack2(wv, wv);
                }
            }
#pragma unroll
            for (int k = 0; k < K1; k++) {
                ulonglong2 ha = *reinterpret_cast<const ulonglong2*>(buf + k*512 + j*2);
                ulonglong2 hb = *reinterpret_cast<const ulonglong2*>(buf + k*512 + j*2 + 4);
                fma2(a0[k], ha.x, pw[0][0]); fma2(a0[k], ha.y, pw[0][1]);
                fma2(a0[k], hb.x, pw[0][2]); fma2(a0[k], hb.y, pw[0][3]);
                fma2(a1[k], ha.x, pw[1][0]); fma2(a1[k], ha.y, pw[1][1]);
                fma2(a1[k], hb.x, pw[1][2]); fma2(a1[k], hb.y, pw[1][3]);
                fma2(a2[k], ha.x, pw[2][0]); fma2(a2[k], ha.y, pw[2][1]);
                fma2(a2[k], hb.x, pw[2][2]); fma2(a2[k], hb.y, pw[2][3]);
                fma2(a3[k], ha.x, pw[3][0]); fma2(a3[k], ha.y, pw[3][1]);
                fma2(a3[k], hb.x, pw[3][2]); fma2(a3[k], hb.y, pw[3][3]);
            }
        }
        __syncthreads();   // all h0 reads done -> overwrite with h1
        const float tb[4] = { tb1[t], tb1[t+64], tb1[t+128], tb1[t+192] };
#pragma unroll
        for (int k = 0; k < K1; k++) {
            float x0, x1;
            unpack2(a0[k], x0, x1);
            *reinterpret_cast<ull*>(buf + k*512 + 2*t)       = pack2(ftanh(x0+tb[0]), ftanh(x1+tb[0]));
            unpack2(a1[k], x0, x1);
            *reinterpret_cast<ull*>(buf + k*512 + 2*(t+64))  = pack2(ftanh(x0+tb[1]), ftanh(x1+tb[1]));
            unpack2(a2[k], x0, x1);
            *reinterpret_cast<ull*>(buf + k*512 + 2*(t+128)) = pack2(ftanh(x0+tb[2]), ftanh(x1+tb[2]));
            unpack2(a3[k], x0, x1);
            *reinterpret_cast<ull*>(buf + k*512 + 2*(t+192)) = pack2(ftanh(x0+tb[3]), ftanh(x1+tb[3]));
        }
        __syncthreads();
    }

    // ---- layer 2: g = exp(tanh(h1 @ tw2 + tb2)); thread owns cols t, t+64 ----
    {
        ull aA[K1], aB[K1];
#pragma unroll
        for (int k = 0; k < K1; k++) { aA[k]=0ull; aB[k]=0ull; }
        for (int j = 0; j < TWd; j += 4) {
            const float* w = tw2 + j*Ww + t;
            ull pwA[4], pwB[4];
#pragma unroll
            for (int jj = 0; jj < 4; jj++) {
                const float va = w[jj*Ww];
                const float vb = w[jj*Ww + 64];
                pwA[jj] = pack2(va, va);
                pwB[jj] = pack2(vb, vb);
            }
#pragma unroll
            for (int k = 0; k < K1; k++) {
                ulonglong2 ha = *reinterpret_cast<const ulonglong2*>(buf + k*512 + j*2);
                ulonglong2 hb = *reinterpret_cast<const ulonglong2*>(buf + k*512 + j*2 + 4);
                fma2(aA[k], ha.x, pwA[0]); fma2(aA[k], ha.y, pwA[1]);
                fma2(aA[k], hb.x, pwA[2]); fma2(aA[k], hb.y, pwA[3]);
                fma2(aB[k], ha.x, pwB[0]); fma2(aB[k], ha.y, pwB[1]);
                fma2(aB[k], hb.x, pwB[2]); fma2(aB[k], hb.y, pwB[3]);
            }
        }
        __syncthreads();   // all h1 reads done -> buf becomes [g | rr]
        const float t2a = tb2[t], t2b = tb2[t+64];
#pragma unroll
        for (int k = 0; k < K1; k++) {
            float x0, x1;
            unpack2(aA[k], x0, x1);
            *reinterpret_cast<ull*>(buf + k*256 + 2*t) =
                pack2(__expf(ftanh(x0+t2a)), __expf(ftanh(x1+t2a)));
            unpack2(aB[k], x0, x1);
            *reinterpret_cast<ull*>(buf + k*256 + 2*(t+64)) =
                pack2(__expf(ftanh(x0+t2b)), __expf(ftanh(x1+t2b)));
        }
        __syncthreads();
    }

    // ---- stage 1: rr from old g rows 1..16; 2 cols/thread ----
    {
        ull rA[K1], rB[K1];
#pragma unroll
        for (int k = 0; k < K1; k++) { rA[k]=0ull; rB[k]=0ull; }
#pragma unroll
        for (int j = 0; j < Kk; j++) {
            const ull gA = *reinterpret_cast<const ull*>(buf + (1+j)*256 + 2*t);
            const ull gB = *reinterpret_cast<const ull*>(buf + (1+j)*256 + 2*(t+64));
#pragma unroll
            for (int k = 0; k < K1; k++) {
                const ull wv = ws2[k*Kk + j];
                fma2(rA[k], gA, wv);
                fma2(rB[k], gB, wv);
            }
        }
#pragma unroll
        for (int k = 0; k < K1; k++) {
            *reinterpret_cast<ull*>(buf + 4352 + k*256 + 2*t)      = rA[k];
            *reinterpret_cast<ull*>(buf + 4352 + k*256 + 2*(t+64)) = rB[k];
        }
        __syncthreads();
    }

    // ---- stage 2: g[k][c] += tanh(sum_w sw0[c][w]*rr[k][w] + sb0[c]); 2 cols ----
    {
        ull sA[K1], sB[K1];
#pragma unroll
        for (int k = 0; k < K1; k++) { sA[k]=0ull; sB[k]=0ull; }
        for (int w = 0; w < Ww; w += 4) {
            const float* sw = d_sw0T + w*Ww + t;
            ull pwA[4], pwB[4];
#pragma unroll
            for (int ww = 0; ww < 4; ww++) {
                const float va = sw[ww*Ww];
                const float vb = sw[ww*Ww + 64];
                pwA[ww] = pack2(va, va);
                pwB[ww] = pack2(vb, vb);
            }
#pragma unroll
            for (int k = 0; k < K1; k++) {
                ulonglong2 ra = *reinterpret_cast<const ulonglong2*>(buf + 4352 + k*256 + w*2);
                ulonglong2 rb = *reinterpret_cast<const ulonglong2*>(buf + 4352 + k*256 + w*2 + 4);
                fma2(sA[k], ra.x, pwA[0]); fma2(sA[k], ra.y, pwA[1]);
                fma2(sA[k], rb.x, pwA[2]); fma2(sA[k], rb.y, pwA[3]);
                fma2(sB[k], ra.x, pwB[0]); fma2(sB[k], ra.y, pwB[1]);
                fma2(sB[k], rb.x, pwB[2]); fma2(sB[k], rb.y, pwB[3]);
            }
        }
        const float sb0a = sb0[t], sb0b = sb0[t+64];
#pragma unroll
        for (int k = 0; k < K1; k++) {
            float a0, a1; unpack2(sA[k], a0, a1);
            ull* gp = reinterpret_cast<ull*>(buf + k*256 + 2*t);
            float g0, g1; unpack2(*gp, g0, g1);
            *gp = pack2(g0 + ftanh(a0+sb0a), g1 + ftanh(a1+sb0a));
            unpack2(sB[k], a0, a1);
            gp = reinterpret_cast<ull*>(buf + k*256 + 2*(t+64));
            unpack2(*gp, g0, g1);
            *gp = pack2(g0 + ftanh(a0+sb0b), g1 + ftanh(a1+sb0b));
        }
        __syncthreads();
    }

    // ---- stage 3: resv2[c] = sum_k rw_v[k] * g'[1+k][c]; 2 cols ----
    {
        ull rvA = 0ull, rvB = 0ull;
#pragma unroll
        for (int k = 0; k < Kk; k++) {
            const ull wv = ws2[k];
            fma2(rvA, *reinterpret_cast<const ull*>(buf + (1+k)*256 + 2*t), wv);
            fma2(rvB, *reinterpret_cast<const ull*>(buf + (1+k)*256 + 2*(t+64)), wv);
        }
        *reinterpret_cast<ull*>(sres + 2*t)      = rvA;
        *reinterpret_cast<ull*>(sres + 2*(t+64)) = rvB;
    }
    __syncthreads();

    // ---- stage 4: green + gdot (2 cols/thread, warp reduce) ----
    {
        ull sa = 0ull, sb = 0ull;
        for (int w = 0; w < Ww; w += 4) {
            const float* sw = d_sw1T + w*Ww + t;
            ulonglong2 ra = *reinterpret_cast<const ulonglong2*>(sres + w*2);
            ulonglong2 rb = *reinterpret_cast<const ulonglong2*>(sres + w*2 + 4);
#pragma unroll
            for (int ww = 0; ww < 4; ww++) {
                const float va = sw[ww*Ww];
                const float vb = sw[ww*Ww + 64];
                const ull r = (ww == 0) ? ra.x : (ww == 1) ? ra.y : (ww == 2) ? rb.x : rb.y;
                fma2(sa, r, pack2(va, va));
                fma2(sb, r, pack2(vb, vb));
            }
        }
        float a0, a1; unpack2(sa, a0, a1);
        float v0, v1; unpack2(*reinterpret_cast<const ull*>(buf + 2*t), v0, v1);
        float p0 = (v0 + ftanh(a0 + sb1[t])) * out_w[t];
        float p1 = (v1 + ftanh(a1 + sb1[t])) * out_w[t];
        unpack2(sb, a0, a1);
        unpack2(*reinterpret_cast<const ull*>(buf + 2*(t+64)), v0, v1);
        p0 += (v0 + ftanh(a0 + sb1[t+64])) * out_w[t+64];
        p1 += (v1 + ftanh(a1 + sb1[t+64])) * out_w[t+64];
#pragma unroll
        for (int o = 16; o > 0; o >>= 1) {
            p0 += __shfl_down_sync(0xffffffffu, p0, o);
            p1 += __shfl_down_sync(0xffffffffu, p1, o);
        }
        if ((t & 31) == 0) { sred[(t>>5)*2] = p0; sred[(t>>5)*2+1] = p1; }
        __syncthreads();
        if (t == 0) {
            d_gdot[(b*Nn+n)*Mm + pair*2 + 0] = sred[0] + sred[2];
            d_gdot[(b*Nn+n)*Mm + pair*2 + 1] = sred[1] + sred[3];
        }
    }
}

// =====================================================================
__global__ void k6_final(const float* __restrict__ boundary,
                         const float* __restrict__ bweights,
                         float* __restrict__ out)
{
    __shared__ float s2[2];
    const int bn = blockIdx.x;
    const int b  = bn >> 5;
    const int t  = threadIdx.x;
    float v = d_gdot[bn*Mm + t] * boundary[b*Mm + t] * bweights[b*Mm + t];
#pragma unroll
    for (int o = 16; o > 0; o >>= 1) v += __shfl_down_sync(0xffffffffu, v, o);
    if ((t & 31) == 0) s2[t >> 5] = v;
    __syncthreads();
    if (t == 0) out[bn] = s2[0] + s2[1];
}

// =====================================================================
extern "C" void kernel_launch(void* const* d_in, const int* in_sizes, int n_in,
                              void* d_out, int out_size)
{
    const float* phase    = (const float*)d_in[0];
    const float* bcoords  = (const float*)d_in[1];
    const float* boundary = (const float*)d_in[2];
    const float* bweights = (const float*)d_in[3];
    const float* posc     = (const float*)d_in[4];
    const float* sigma    = (const float*)d_in[5];
    const float* velc     = (const float*)d_in[6];
    const float* vwt      = (const float*)d_in[7];
    const float* scat     = (const float*)d_in[8];
    const float* sscat    = (const float*)d_in[9];
    const float* aw0 = (const float*)d_in[10];
    const float* ab0 = (const float*)d_in[11];
    const float* aw1 = (const float*)d_in[12];
    const float* ab1 = (const float*)d_in[13];
    const float* aw2 = (const float*)d_in[14];
    const float* ab2 = (const float*)d_in[15];
    const float* tw0 = (const float*)d_in[16];
    const float* tb0 = (const float*)d_in[17];
    const float* tw1 = (const float*)d_in[18];
    const float* tb1 = (const float*)d_in[19];
    const float* tw2 = (const float*)d_in[20];
    const float* tb2 = (const float*)d_in[21];
    const float* sw0 = (const float*)d_in[22];
    const float* sb0 = (const float*)d_in[23];
    const float* sw1 = (const float*)d_in[24];
    const float* sb1 = (const float*)d_in[25];
    const float* ow  = (const float*)d_in[26];
    float* out = (float*)d_out;

    k_tr<<<64, 256>>>(sw0, sw1);
    k1_attn<<<Bb*Nn*K1, 128>>>(phase, posc, sigma, velc,
                               aw0, ab0, aw1, ab1, aw2, ab2, tw0, tb0);
    k_bm<<<Bb*Mm, TWd>>>(bcoords, tw0);
    k4_main<<<Bb*Nn*(Mm/2), 64>>>(
        scat, sscat, vwt, tw1, tb1, tw2, tb2, sb0, sb1, ow);
    k6_final<<<Bb*Nn, 64>>>(boundary, bweights, out);
}

// round 6
// speedup vs baseline: 1.4069x; 1.4069x over previous
#include <cuda_runtime.h>
#include <math.h>

#define Bb 4
#define Nn 32
#define Mm 64
#define Kk 16
#define K1 17
#define Pp 128
#define Ww 128
#define TWd 256

typedef unsigned long long ull;

// ---------- f32x2 helpers ----------
__device__ __forceinline__ ull pack2(float a, float b) {
    ull r; asm("mov.b64 %0, {%1, %2};" : "=l"(r) : "f"(a), "f"(b)); return r;
}
__device__ __forceinline__ void unpack2(ull v, float& a, float& b) {
    asm("mov.b64 {%0, %1}, %2;" : "=f"(a), "=f"(b) : "l"(v));
}
__device__ __forceinline__ void fma2(ull& d, ull a, ull b) {
    asm("fma.rn.f32x2 %0, %1, %2, %0;" : "+l"(d) : "l"(a), "l"(b));
}
__device__ __forceinline__ ull add2(ull a, ull b) {
    ull r; asm("add.rn.f32x2 %0, %1, %2;" : "=l"(r) : "l"(a), "l"(b)); return r;
}
// exact identity tanh = 1 - 2/(exp(2x)+1); only error is __expf rounding (~2^-21)
__device__ __forceinline__ float ftanh(float x) {
    float e = __expf(2.0f * x);
    return 1.0f - __fdividef(2.0f, e + 1.0f);
}

// ------- scratch (device globals; no runtime allocation) -------
__device__ float d_A[Bb*Nn*K1*TWd];
__device__ float d_Bm[Bb*Mm*TWd];
__device__ float d_gdot[Bb*Nn*Mm];
__device__ float d_sw0T[Ww*Ww];   // [w][i]
__device__ float d_sw1T[Ww*Ww];   // [w][i]

// =====================================================================
// K_tr: transpose sw0/sw1 for coalesced column access in stages 2/4
// =====================================================================
__global__ void k_tr(const float* __restrict__ sw0, const float* __restrict__ sw1)
{
    const int idx = blockIdx.x*256 + threadIdx.x;  // 0..16383
    const int i = idx >> 7, w = idx & 127;
    d_sw0T[w*Ww + i] = sw0[idx];
    d_sw1T[w*Ww + i] = sw1[idx];
}

// =====================================================================
// K1: attention MLP + softmax + coeff + A-partial.  One block per (b,n,k1).
// =====================================================================
__global__ void __launch_bounds__(128) k1_attn(
    const float* __restrict__ phase, const float* __restrict__ posc,
    const float* __restrict__ sigma, const float* __restrict__ velc,
    const float* __restrict__ aw0, const float* __restrict__ ab0,
    const float* __restrict__ aw1, const float* __restrict__ ab1,
    const float* __restrict__ aw2, const float* __restrict__ ab2,
    const float* __restrict__ tw0, const float* __restrict__ tb0)
{
    __shared__ float s_aw0[6*64];
    __shared__ float s_ab0[64];
    __shared__ float s_aw1[64*64];
    __shared__ float s_ab1[64];
    __shared__ float s_aw2[64];
    __shared__ float red[128];

    const int bx = blockIdx.x;
    const int k1 = bx % K1;
    const int n  = (bx / K1) % Nn;
    const int b  = bx / (K1*Nn);
    const int t  = threadIdx.x;

    for (int i = t; i < 6*64; i += 128) s_aw0[i] = aw0[i];
    if (t < 64) { s_ab0[t] = ab0[t]; s_aw2[t] = aw2[t]; s_ab1[t] = ab1[t]; }
    for (int i = t; i < 64*64; i += 128) s_aw1[i] = aw1[i];
    __syncthreads();

    const float x0 = phase[(b*Nn+n)*4 + 0];
    const float x1 = phase[(b*Nn+n)*4 + 1];
    float va0, va1;
    if (k1 == 0) { va0 = phase[(b*Nn+n)*4 + 2]; va1 = phase[(b*Nn+n)*4 + 3]; }
    else         { va0 = velc[(b*Kk + (k1-1))*2 + 0]; va1 = velc[(b*Kk + (k1-1))*2 + 1]; }
    const float inv = rsqrtf(va0*va0 + va1*va1 + 1e-16f);
    const float ag0 = va0*inv, ag1 = va1*inv;

    const float rx = x0 - posc[(b*Pp + t)*2 + 0];
    const float ry = x1 - posc[(b*Pp + t)*2 + 1];
    const float rd = sqrtf(rx*rx + ry*ry + 1e-16f);
    const float pl = rx*ag0 + ry*ag1;
    const float al = pl / (rd + 1e-8f);

    float h0[64];
#pragma unroll
    for (int j = 0; j < 64; j++) {
        h0[j] = ftanh(s_ab0[j] + x0*s_aw0[0*64+j] + x1*s_aw0[1*64+j]
                              + va0*s_aw0[2*64+j] + va1*s_aw0[3*64+j]
                              + al*s_aw0[4*64+j] + pl*s_aw0[5*64+j]);
    }
    float logit = ab2[0];
#pragma unroll
    for (int g = 0; g < 4; g++) {
        ull acc[8];
#pragma unroll
        for (int p = 0; p < 8; p++) acc[p] = 0ull;
        for (int j = 0; j < 64; j++) {
            const ull hp = pack2(h0[j], h0[j]);
            const float* wrow = &s_aw1[j*64 + g*16];
            ulonglong2 wA = *reinterpret_cast<const ulonglong2*>(wrow + 0);
            ulonglong2 wB = *reinterpret_cast<const ulonglong2*>(wrow + 4);
            ulonglong2 wC = *reinterpret_cast<const ulonglong2*>(wrow + 8);
            ulonglong2 wD = *reinterpret_cast<const ulonglong2*>(wrow + 12);
            fma2(acc[0], hp, wA.x); fma2(acc[1], hp, wA.y);
            fma2(acc[2], hp, wB.x); fma2(acc[3], hp, wB.y);
            fma2(acc[4], hp, wC.x); fma2(acc[5], hp, wC.y);
            fma2(acc[6], hp, wD.x); fma2(acc[7], hp, wD.y);
        }
#pragma unroll
        for (int p = 0; p < 8; p++) {
            const int i = g*16 + p*2;
            float a0, a1; unpack2(acc[p], a0, a1);
            logit += ftanh(a0 + s_ab1[i])   * s_aw2[i]
                   + ftanh(a1 + s_ab1[i+1]) * s_aw2[i+1];
        }
    }

    float lg = (pl > 0.0f) ? logit : -1e30f;
    red[t] = lg; __syncthreads();
    for (int s = 64; s > 0; s >>= 1) { if (t < s) red[t] = fmaxf(red[t], red[t+s]); __syncthreads(); }
    const float mx = red[0]; __syncthreads();
    const float e = __expf(lg - mx);
    red[t] = e; __syncthreads();
    for (int s = 64; s > 0; s >>= 1) { if (t < s) red[t] += red[t+s]; __syncthreads(); }
    const float denom = red[0]; __syncthreads();
    const float aw = e / denom;

    const float sg0 = sigma[(b*Pp+t)*2 + 0];
    const float sg1 = sigma[(b*Pp+t)*2 + 1];
    red[t] = aw*sg0; __syncthreads();
    for (int s = 64; s > 0; s >>= 1) { if (t < s) red[t] += red[t+s]; __syncthreads(); }
    const float sum0 = red[0]; __syncthreads();
    red[t] = aw*sg1; __syncthreads();
    for (int s = 64; s > 0; s >>= 1) { if (t < s) red[t] += red[t+s]; __syncthreads(); }
    const float sum1 = red[0]; __syncthreads();

    const float c0 = __expf(-sum0);
    const float c1 = __expf(-sum1);

    for (int tt = t; tt < TWd; tt += 128) {
        float a = tb0[tt]
                + x0*tw0[0*TWd+tt] + x1*tw0[1*TWd+tt]
                + va0*tw0[2*TWd+tt] + va1*tw0[3*TWd+tt]
                + c0*tw0[8*TWd+tt] + c1*tw0[9*TWd+tt];
        d_A[bx*TWd + tt] = a;
    }
}

// =====================================================================
__global__ void k_bm(const float* __restrict__ bcoords, const float* __restrict__ tw0)
{
    const int bm = blockIdx.x;
    const int t  = threadIdx.x;
    const float xp0 = bcoords[bm*4+0], xp1 = bcoords[bm*4+1];
    const float vp0 = bcoords[bm*4+2], vp1 = bcoords[bm*4+3];
    d_Bm[bm*TWd + t] = xp0*tw0[4*TWd+t] + xp1*tw0[5*TWd+t]
                     + vp0*tw0[6*TWd+t] + vp1*tw0[7*TWd+t];
}

// =====================================================================
// K4: transport MLP + scattering chain. Round-3 shape (128 threads,
// 2 cols/thread in layer1) + (a) 2 m-pairs per block, (b) register
// double-buffer prefetch of weights (hides L2 latency), (c) transposed
// sw0/sw1 for coalesced stage-2/4 weight loads.
// =====================================================================
__global__ void __launch_bounds__(128) k4_main(
    const float* __restrict__ scat, const float* __restrict__ sscat,
    const float* __restrict__ vwt,
    const float* __restrict__ tw1, const float* __restrict__ tb1,
    const float* __restrict__ tw2, const float* __restrict__ tb2,
    const float* __restrict__ sb0, const float* __restrict__ sb1,
    const float* __restrict__ out_w)
{
    __shared__ float buf[8704];      // h0(17x512) -> h1(17x512) -> [g(17x256)|rr(17x256)]
    __shared__ ull   ws2[272];
    __shared__ float sres[256];
    __shared__ float sred[8];

    const int bx   = blockIdx.x;              // 0..2047
    const int quad = bx & 15;                 // 2 m-pairs per block
    const int n    = (bx >> 4) & 31;
    const int b    = bx >> 9;
    const int t    = threadIdx.x;             // 0..127

    for (int i = t; i < 272; i += 128) {
        const int row = i >> 4, j = i & 15;
        float v = (row == 0) ? (1.0f - scat[(b*Nn+n)*Kk + j])
                             : (1.0f - sscat[b*256 + (row-1)*Kk + j]);
        v *= vwt[b*Kk + j];
        ws2[i] = pack2(v, v);
    }

    const float* Arow = d_A + (b*Nn + n)*K1*TWd;
    const float  t1a = tb1[t], t1b = tb1[t+128];
    const float  tb2c = tb2[t];
    const float  sb0c = sb0[t];
    const float  sb1c = sb1[t];
    const float  owc  = out_w[t];

    for (int mm = 0; mm < 2; mm++) {
        const int pair = quad*2 + mm;

        // ---- layer 0: h0 pairs ----
        {
            const float* bm0 = d_Bm + (b*Mm + pair*2 + 0)*TWd;
            const float* bm1 = bm0 + TWd;
            const float b0a = bm0[t], b0b = bm0[t+128];
            const float b1a = bm1[t], b1b = bm1[t+128];
#pragma unroll
            for (int k = 0; k < K1; k++) {
                const float A0 = Arow[k*TWd + t];
                const float A1 = Arow[k*TWd + t + 128];
                *reinterpret_cast<ull*>(buf + k*512 + 2*t) =
                    pack2(ftanh(A0 + b0a), ftanh(A0 + b1a));
                *reinterpret_cast<ull*>(buf + k*512 + 2*(t+128)) =
                    pack2(ftanh(A1 + b0b), ftanh(A1 + b1b));
            }
        }
        __syncthreads();

        // ---- layer 1: h1 = tanh(h0 @ tw1 + tb1); cols t, t+128; prefetched weights ----
        {
            ull acc0[K1], acc1[K1];
#pragma unroll
            for (int k = 0; k < K1; k++) { acc0[k] = 0ull; acc1[k] = 0ull; }
            const float* wb = tw1 + t;
            float wc[8], wn[8];
#pragma unroll
            for (int jj = 0; jj < 4; jj++) { wc[jj] = wb[jj*TWd]; wc[4+jj] = wb[jj*TWd + 128]; }
#pragma unroll 1
            for (int j = 0; j < TWd; j += 4) {
                if (j + 4 < TWd) {
                    const float* wp = wb + (j+4)*TWd;
#pragma unroll
                    for (int jj = 0; jj < 4; jj++) { wn[jj] = wp[jj*TWd]; wn[4+jj] = wp[jj*TWd + 128]; }
                }
                const ull pa0 = pack2(wc[0],wc[0]), pa1 = pack2(wc[1],wc[1]),
                          pa2 = pack2(wc[2],wc[2]), pa3 = pack2(wc[3],wc[3]);
                const ull pc0 = pack2(wc[4],wc[4]), pc1 = pack2(wc[5],wc[5]),
                          pc2 = pack2(wc[6],wc[6]), pc3 = pack2(wc[7],wc[7]);
#pragma unroll
                for (int k = 0; k < K1; k++) {
                    ulonglong2 ha = *reinterpret_cast<const ulonglong2*>(buf + k*512 + j*2);
                    ulonglong2 hb = *reinterpret_cast<const ulonglong2*>(buf + k*512 + j*2 + 4);
                    fma2(acc0[k], ha.x, pa0); fma2(acc0[k], ha.y, pa1);
                    fma2(acc0[k], hb.x, pa2); fma2(acc0[k], hb.y, pa3);
                    fma2(acc1[k], ha.x, pc0); fma2(acc1[k], ha.y, pc1);
                    fma2(acc1[k], hb.x, pc2); fma2(acc1[k], hb.y, pc3);
                }
#pragma unroll
                for (int q = 0; q < 8; q++) wc[q] = wn[q];
            }
            __syncthreads();
#pragma unroll
            for (int k = 0; k < K1; k++) {
                float x0, x1; unpack2(acc0[k], x0, x1);
                float y0, y1; unpack2(acc1[k], y0, y1);
                *reinterpret_cast<ull*>(buf + k*512 + 2*t) =
                    pack2(ftanh(x0+t1a), ftanh(x1+t1a));
                *reinterpret_cast<ull*>(buf + k*512 + 2*(t+128)) =
                    pack2(ftanh(y0+t1b), ftanh(y1+t1b));
            }
            __syncthreads();
        }

        // ---- layer 2: g = exp(tanh(h1 @ tw2 + tb2)); col t; prefetched weights ----
        {
            ull acc[K1];
#pragma unroll
            for (int k = 0; k < K1; k++) acc[k] = 0ull;
            const float* wb = tw2 + t;
            float wc[4], wn[4];
#pragma unroll
            for (int jj = 0; jj < 4; jj++) wc[jj] = wb[jj*Ww];
#pragma unroll 1
            for (int j = 0; j < TWd; j += 4) {
                if (j + 4 < TWd) {
                    const float* wp = wb + (j+4)*Ww;
#pragma unroll
                    for (int jj = 0; jj < 4; jj++) wn[jj] = wp[jj*Ww];
                }
                const ull p0 = pack2(wc[0],wc[0]), p1 = pack2(wc[1],wc[1]),
                          p2 = pack2(wc[2],wc[2]), p3 = pack2(wc[3],wc[3]);
#pragma unroll
                for (int k = 0; k < K1; k++) {
                    ulonglong2 ha = *reinterpret_cast<const ulonglong2*>(buf + k*512 + j*2);
                    ulonglong2 hb = *reinterpret_cast<const ulonglong2*>(buf + k*512 + j*2 + 4);
                    fma2(acc[k], ha.x, p0); fma2(acc[k], ha.y, p1);
                    fma2(acc[k], hb.x, p2); fma2(acc[k], hb.y, p3);
                }
#pragma unroll
                for (int q = 0; q < 4; q++) wc[q] = wn[q];
            }
            __syncthreads();
#pragma unroll
            for (int k = 0; k < K1; k++) {
                float x0, x1; unpack2(acc[k], x0, x1);
                *reinterpret_cast<ull*>(buf + k*256 + 2*t) =
                    pack2(__expf(ftanh(x0+tb2c)), __expf(ftanh(x1+tb2c)));
            }
            __syncthreads();
        }

        // ---- stage 1: rr[0]=res_v, rr[1+i]=res2[i] from old g rows 1..16 ----
        {
            ull r[K1];
#pragma unroll
            for (int k = 0; k < K1; k++) r[k] = 0ull;
#pragma unroll
            for (int j = 0; j < Kk; j++) {
                const ull g2 = *reinterpret_cast<const ull*>(buf + (1+j)*256 + 2*t);
#pragma unroll
                for (int k = 0; k < K1; k++)
                    fma2(r[k], g2, ws2[k*Kk + j]);
            }
#pragma unroll
            for (int k = 0; k < K1; k++)
                *reinterpret_cast<ull*>(buf + 4352 + k*256 + 2*t) = r[k];
            __syncthreads();
        }

        // ---- stage 2: g[k][t] += tanh(sum_w sw0T[w][t]*rr[k][w] + sb0[t]) ----
        {
            ull s2[K1];
#pragma unroll
            for (int k = 0; k < K1; k++) s2[k] = 0ull;
            const float* wb = d_sw0T + t;
            float wc[4], wn[4];
#pragma unroll
            for (int ww = 0; ww < 4; ww++) wc[ww] = wb[ww*Ww];
#pragma unroll 1
            for (int w = 0; w < Ww; w += 4) {
                if (w + 4 < Ww) {
                    const float* wp = wb + (w+4)*Ww;
#pragma unroll
                    for (int ww = 0; ww < 4; ww++) wn[ww] = wp[ww*Ww];
                }
                const ull p0 = pack2(wc[0],wc[0]), p1 = pack2(wc[1],wc[1]),
                          p2 = pack2(wc[2],wc[2]), p3 = pack2(wc[3],wc[3]);
#pragma unroll
                for (int k = 0; k < K1; k++) {
                    ulonglong2 ra = *reinterpret_cast<const ulonglong2*>(buf + 4352 + k*256 + w*2);
                    ulonglong2 rb = *reinterpret_cast<const ulonglong2*>(buf + 4352 + k*256 + w*2 + 4);
                    fma2(s2[k], ra.x, p0); fma2(s2[k], ra.y, p1);
                    fma2(s2[k], rb.x, p2); fma2(s2[k], rb.y, p3);
                }
#pragma unroll
                for (int q = 0; q < 4; q++) wc[q] = wn[q];
            }
#pragma unroll
            for (int k = 0; k < K1; k++) {
                float a0, a1; unpack2(s2[k], a0, a1);
                ull* gp = reinterpret_cast<ull*>(buf + k*256 + 2*t);
                float g0, g1; unpack2(*gp, g0, g1);
                *gp = pack2(g0 + ftanh(a0+sb0c), g1 + ftanh(a1+sb0c));
            }
            __syncthreads();
        }

        // ---- stage 3: resv2[t] = sum_k rw_v[k] * g'[1+k][t] ----
        {
            ull rv = 0ull;
#pragma unroll
            for (int k = 0; k < Kk; k++)
                fma2(rv, *reinterpret_cast<const ull*>(buf + (1+k)*256 + 2*t), ws2[k]);
            *reinterpret_cast<ull*>(sres + 2*t) = rv;
        }
        __syncthreads();

        // ---- stage 4: green = g'[0] + tanh(sw1T[:,t]@resv2 + sb1); gdot ----
        {
            ull sa = 0ull, sb = 0ull;
            const float* wb = d_sw1T + t;
#pragma unroll 1
            for (int w = 0; w < Ww; w += 4) {
                const float v0w = wb[(w+0)*Ww];
                const float v1w = wb[(w+1)*Ww];
                const float v2w = wb[(w+2)*Ww];
                const float v3w = wb[(w+3)*Ww];
                ulonglong2 ra = *reinterpret_cast<const ulonglong2*>(sres + w*2);
                ulonglong2 rb = *reinterpret_cast<const ulonglong2*>(sres + w*2 + 4);
                fma2(sa, ra.x, pack2(v0w,v0w)); fma2(sb, ra.y, pack2(v1w,v1w));
                fma2(sa, rb.x, pack2(v2w,v2w)); fma2(sb, rb.y, pack2(v3w,v3w));
            }
            const ull tot = add2(sa, sb);
            float a0, a1; unpack2(tot, a0, a1);
            float v0, v1; unpack2(*reinterpret_cast<const ull*>(buf + 2*t), v0, v1);
            float p0 = (v0 + ftanh(a0+sb1c)) * owc;
            float p1 = (v1 + ftanh(a1+sb1c)) * owc;
#pragma unroll
            for (int o = 16; o > 0; o >>= 1) {
                p0 += __shfl_down_sync(0xffffffffu, p0, o);
                p1 += __shfl_down_sync(0xffffffffu, p1, o);
            }
            if ((t & 31) == 0) { sred[(t>>5)*2] = p0; sred[(t>>5)*2+1] = p1; }
            __syncthreads();
            if (t == 0) {
                d_gdot[(b*Nn+n)*Mm + pair*2 + 0] = sred[0]+sred[2]+sred[4]+sred[6];
                d_gdot[(b*Nn+n)*Mm + pair*2 + 1] = sred[1]+sred[3]+sred[5]+sred[7];
            }
            __syncthreads();
        }
    }
}

// =====================================================================
__global__ void k6_final(const float* __restrict__ boundary,
                         const float* __restrict__ bweights,
                         float* __restrict__ out)
{
    __shared__ float s2[2];
    const int bn = blockIdx.x;
    const int b  = bn >> 5;
    const int t  = threadIdx.x;
    float v = d_gdot[bn*Mm + t] * boundary[b*Mm + t] * bweights[b*Mm + t];
#pragma unroll
    for (int o = 16; o > 0; o >>= 1) v += __shfl_down_sync(0xffffffffu, v, o);
    if ((t & 31) == 0) s2[t >> 5] = v;
    __syncthreads();
    if (t == 0) out[bn] = s2[0] + s2[1];
}

// =====================================================================
extern "C" void kernel_launch(void* const* d_in, const int* in_sizes, int n_in,
                              void* d_out, int out_size)
{
    const float* phase    = (const float*)d_in[0];
    const float* bcoords  = (const float*)d_in[1];
    const float* boundary = (const float*)d_in[2];
    const float* bweights = (const float*)d_in[3];
    const float* posc     = (const float*)d_in[4];
    const float* sigma    = (const float*)d_in[5];
    const float* velc     = (const float*)d_in[6];
    const float* vwt      = (const float*)d_in[7];
    const float* scat     = (const float*)d_in[8];
    const float* sscat    = (const float*)d_in[9];
    const float* aw0 = (const float*)d_in[10];
    const float* ab0 = (const float*)d_in[11];
    const float* aw1 = (const float*)d_in[12];
    const float* ab1 = (const float*)d_in[13];
    const float* aw2 = (const float*)d_in[14];
    const float* ab2 = (const float*)d_in[15];
    const float* tw0 = (const float*)d_in[16];
    const float* tb0 = (const float*)d_in[17];
    const float* tw1 = (const float*)d_in[18];
    const float* tb1 = (const float*)d_in[19];
    const float* tw2 = (const float*)d_in[20];
    const float* tb2 = (const float*)d_in[21];
    const float* sw0 = (const float*)d_in[22];
    const float* sb0 = (const float*)d_in[23];
    const float* sw1 = (const float*)d_in[24];
    const float* sb1 = (const float*)d_in[25];
    const float* ow  = (const float*)d_in[26];
    float* out = (float*)d_out;

    k_tr<<<64, 256>>>(sw0, sw1);
    k1_attn<<<Bb*Nn*K1, 128>>>(phase, posc, sigma, velc,
                               aw0, ab0, aw1, ab1, aw2, ab2, tw0, tb0);
    k_bm<<<Bb*Mm, TWd>>>(bcoords, tw0);
    k4_main<<<Bb*Nn*(Mm/4), 128>>>(
        scat, sscat, vwt, tw1, tb1, tw2, tb2, sb0, sb1, ow);
    k6_final<<<Bb*Nn, 64>>>(boundary, bweights, out);
}

// round 7
// speedup vs baseline: 1.5412x; 1.0954x over previous
#include <cuda_runtime.h>
#include <math.h>

#define Bb 4
#define Nn 32
#define Mm 64
#define Kk 16
#define K1 17
#define Pp 128
#define Ww 128
#define TWd 256

typedef unsigned long long ull;

// ---------- f32x2 helpers ----------
__device__ __forceinline__ ull pack2(float a, float b) {
    ull r; asm("mov.b64 %0, {%1, %2};" : "=l"(r) : "f"(a), "f"(b)); return r;
}
__device__ __forceinline__ void unpack2(ull v, float& a, float& b) {
    asm("mov.b64 {%0, %1}, %2;" : "=f"(a), "=f"(b) : "l"(v));
}
__device__ __forceinline__ void fma2(ull& d, ull a, ull b) {
    asm("fma.rn.f32x2 %0, %1, %2, %0;" : "+l"(d) : "l"(a), "l"(b));
}
__device__ __forceinline__ ull add2(ull a, ull b) {
    ull r; asm("add.rn.f32x2 %0, %1, %2;" : "=l"(r) : "l"(a), "l"(b)); return r;
}
// exact identity tanh = 1 - 2/(exp(2x)+1); only error is __expf rounding (~2^-21)
__device__ __forceinline__ float ftanh(float x) {
    float e = __expf(2.0f * x);
    return 1.0f - __fdividef(2.0f, e + 1.0f);
}

// ------- scratch (device globals; no runtime allocation) -------
__device__ float d_A[Bb*Nn*K1*TWd];
__device__ float d_Bm[Bb*Mm*TWd];
__device__ float d_gdot[Bb*Nn*Mm];
__device__ float d_sw0T[Ww*Ww];   // [w][i]
__device__ float d_sw1T[Ww*Ww];   // [w][i]

// =====================================================================
// K_tr: transpose sw0/sw1 for coalesced column access in stages 2/4
// =====================================================================
__global__ void k_tr(const float* __restrict__ sw0, const float* __restrict__ sw1)
{
    const int idx = blockIdx.x*256 + threadIdx.x;  // 0..16383
    const int i = idx >> 7, w = idx & 127;
    d_sw0T[w*Ww + i] = sw0[idx];
    d_sw1T[w*Ww + i] = sw1[idx];
}

// =====================================================================
// K1: attention MLP + softmax + coeff + A-partial.  One block per (b,n,k1).
// =====================================================================
__global__ void __launch_bounds__(128) k1_attn(
    const float* __restrict__ phase, const float* __restrict__ posc,
    const float* __restrict__ sigma, const float* __restrict__ velc,
    const float* __restrict__ aw0, const float* __restrict__ ab0,
    const float* __restrict__ aw1, const float* __restrict__ ab1,
    const float* __restrict__ aw2, const float* __restrict__ ab2,
    const float* __restrict__ tw0, const float* __restrict__ tb0)
{
    __shared__ float s_aw0[6*64];
    __shared__ float s_ab0[64];
    __shared__ float s_aw1[64*64];
    __shared__ float s_ab1[64];
    __shared__ float s_aw2[64];
    __shared__ float red[128];

    const int bx = blockIdx.x;
    const int k1 = bx % K1;
    const int n  = (bx / K1) % Nn;
    const int b  = bx / (K1*Nn);
    const int t  = threadIdx.x;

    for (int i = t; i < 6*64; i += 128) s_aw0[i] = aw0[i];
    if (t < 64) { s_ab0[t] = ab0[t]; s_aw2[t] = aw2[t]; s_ab1[t] = ab1[t]; }
    for (int i = t; i < 64*64; i += 128) s_aw1[i] = aw1[i];
    __syncthreads();

    const float x0 = phase[(b*Nn+n)*4 + 0];
    const float x1 = phase[(b*Nn+n)*4 + 1];
    float va0, va1;
    if (k1 == 0) { va0 = phase[(b*Nn+n)*4 + 2]; va1 = phase[(b*Nn+n)*4 + 3]; }
    else         { va0 = velc[(b*Kk + (k1-1))*2 + 0]; va1 = velc[(b*Kk + (k1-1))*2 + 1]; }
    const float inv = rsqrtf(va0*va0 + va1*va1 + 1e-16f);
    const float ag0 = va0*inv, ag1 = va1*inv;

    const float rx = x0 - posc[(b*Pp + t)*2 + 0];
    const float ry = x1 - posc[(b*Pp + t)*2 + 1];
    const float rd = sqrtf(rx*rx + ry*ry + 1e-16f);
    const float pl = rx*ag0 + ry*ag1;
    const float al = pl / (rd + 1e-8f);

    float h0[64];
#pragma unroll
    for (int j = 0; j < 64; j++) {
        h0[j] = ftanh(s_ab0[j] + x0*s_aw0[0*64+j] + x1*s_aw0[1*64+j]
                              + va0*s_aw0[2*64+j] + va1*s_aw0[3*64+j]
                              + al*s_aw0[4*64+j] + pl*s_aw0[5*64+j]);
    }
    float logit = ab2[0];
#pragma unroll
    for (int g = 0; g < 4; g++) {
        ull acc[8];
#pragma unroll
        for (int p = 0; p < 8; p++) acc[p] = 0ull;
        for (int j = 0; j < 64; j++) {
            const ull hp = pack2(h0[j], h0[j]);
            const float* wrow = &s_aw1[j*64 + g*16];
            ulonglong2 wA = *reinterpret_cast<const ulonglong2*>(wrow + 0);
            ulonglong2 wB = *reinterpret_cast<const ulonglong2*>(wrow + 4);
            ulonglong2 wC = *reinterpret_cast<const ulonglong2*>(wrow + 8);
            ulonglong2 wD = *reinterpret_cast<const ulonglong2*>(wrow + 12);
            fma2(acc[0], hp, wA.x); fma2(acc[1], hp, wA.y);
            fma2(acc[2], hp, wB.x); fma2(acc[3], hp, wB.y);
            fma2(acc[4], hp, wC.x); fma2(acc[5], hp, wC.y);
            fma2(acc[6], hp, wD.x); fma2(acc[7], hp, wD.y);
        }
#pragma unroll
        for (int p = 0; p < 8; p++) {
            const int i = g*16 + p*2;
            float a0, a1; unpack2(acc[p], a0, a1);
            logit += ftanh(a0 + s_ab1[i])   * s_aw2[i]
                   + ftanh(a1 + s_ab1[i+1]) * s_aw2[i+1];
        }
    }

    float lg = (pl > 0.0f) ? logit : -1e30f;
    red[t] = lg; __syncthreads();
    for (int s = 64; s > 0; s >>= 1) { if (t < s) red[t] = fmaxf(red[t], red[t+s]); __syncthreads(); }
    const float mx = red[0]; __syncthreads();
    const float e = __expf(lg - mx);
    red[t] = e; __syncthreads();
    for (int s = 64; s > 0; s >>= 1) { if (t < s) red[t] += red[t+s]; __syncthreads(); }
    const float denom = red[0]; __syncthreads();
    const float aw = e / denom;

    const float sg0 = sigma[(b*Pp+t)*2 + 0];
    const float sg1 = sigma[(b*Pp+t)*2 + 1];
    red[t] = aw*sg0; __syncthreads();
    for (int s = 64; s > 0; s >>= 1) { if (t < s) red[t] += red[t+s]; __syncthreads(); }
    const float sum0 = red[0]; __syncthreads();
    red[t] = aw*sg1; __syncthreads();
    for (int s = 64; s > 0; s >>= 1) { if (t < s) red[t] += red[t+s]; __syncthreads(); }
    const float sum1 = red[0]; __syncthreads();

    const float c0 = __expf(-sum0);
    const float c1 = __expf(-sum1);

    for (int tt = t; tt < TWd; tt += 128) {
        float a = tb0[tt]
                + x0*tw0[0*TWd+tt] + x1*tw0[1*TWd+tt]
                + va0*tw0[2*TWd+tt] + va1*tw0[3*TWd+tt]
                + c0*tw0[8*TWd+tt] + c1*tw0[9*TWd+tt];
        d_A[bx*TWd + tt] = a;
    }
}

// =====================================================================
__global__ void k_bm(const float* __restrict__ bcoords, const float* __restrict__ tw0)
{
    const int bm = blockIdx.x;
    const int t  = threadIdx.x;
    const float xp0 = bcoords[bm*4+0], xp1 = bcoords[bm*4+1];
    const float vp0 = bcoords[bm*4+2], vp1 = bcoords[bm*4+3];
    d_Bm[bm*TWd + t] = xp0*tw0[4*TWd+t] + xp1*tw0[5*TWd+t]
                     + vp0*tw0[6*TWd+t] + vp1*tw0[7*TWd+t];
}

// =====================================================================
// K4: transport MLP + scattering chain.
//  - layer1: two sequential k-passes (rows 0..8, 9..16), 2 cols/thread,
//    prefetched weights -> low register pressure, FMA-bound.
//  - layer2/stage2: k-split across thread halves + 2 cols/thread ->
//    0.36 wf per fma2 (was 0.56) -> no longer L1-bound.
//  - 4 blocks/SM via __launch_bounds__(128, 4).
// =====================================================================
__global__ void __launch_bounds__(128, 4) k4_main(
    const float* __restrict__ scat, const float* __restrict__ sscat,
    const float* __restrict__ vwt,
    const float* __restrict__ tw1, const float* __restrict__ tb1,
    const float* __restrict__ tw2, const float* __restrict__ tb2,
    const float* __restrict__ sb0, const float* __restrict__ sb1,
    const float* __restrict__ out_w)
{
    __shared__ float buf[8704];      // h0(17x512) -> h1(17x512) -> [g(17x256)|rr(17x256)]
    __shared__ ull   ws2[272];
    __shared__ float sres[256];
    __shared__ float sred[8];

    const int bx   = blockIdx.x;              // 0..2047
    const int quad = bx & 15;                 // 2 m-pairs per block
    const int n    = (bx >> 4) & 31;
    const int b    = bx >> 9;
    const int t    = threadIdx.x;             // 0..127
    const int th   = t >> 6;                  // half for k-split stages
    const int tc   = t & 63;
    const int kbs  = th ? 9 : 0;              // k-row base for this half
    const int kcs  = th ? 8 : 9;              // k-row count for this half

    for (int i = t; i < 272; i += 128) {
        const int row = i >> 4, j = i & 15;
        float v = (row == 0) ? (1.0f - scat[(b*Nn+n)*Kk + j])
                             : (1.0f - sscat[b*256 + (row-1)*Kk + j]);
        v *= vwt[b*Kk + j];
        ws2[i] = pack2(v, v);
    }

    const float* Arow = d_A + (b*Nn + n)*K1*TWd;
    const float  t1a = tb1[t], t1b = tb1[t+128];
    const float  tb2a = tb2[tc], tb2b = tb2[tc+64];
    const float  sb0a = sb0[tc], sb0b = sb0[tc+64];
    const float  sb1c = sb1[t];
    const float  owc  = out_w[t];

    for (int mm = 0; mm < 2; mm++) {
        const int pair = quad*2 + mm;

        // ---- layer 0: h0 pairs ----
        {
            const float* bm0 = d_Bm + (b*Mm + pair*2 + 0)*TWd;
            const float* bm1 = bm0 + TWd;
            const float b0a = bm0[t], b0b = bm0[t+128];
            const float b1a = bm1[t], b1b = bm1[t+128];
#pragma unroll
            for (int k = 0; k < K1; k++) {
                const float A0 = Arow[k*TWd + t];
                const float A1 = Arow[k*TWd + t + 128];
                *reinterpret_cast<ull*>(buf + k*512 + 2*t) =
                    pack2(ftanh(A0 + b0a), ftanh(A0 + b1a));
                *reinterpret_cast<ull*>(buf + k*512 + 2*(t+128)) =
                    pack2(ftanh(A1 + b0b), ftanh(A1 + b1b));
            }
        }
        __syncthreads();

        // ---- layer 1: two k-passes; cols t, t+128; prefetched weights ----
#pragma unroll
        for (int pass = 0; pass < 2; pass++) {
            const int kb = pass ? 9 : 0;
            const int kc = pass ? 8 : 9;
            ull acc0[9], acc1[9];
#pragma unroll
            for (int k = 0; k < 9; k++) { acc0[k] = 0ull; acc1[k] = 0ull; }
            const float* wb = tw1 + t;
            float wc[8], wn[8];
#pragma unroll
            for (int jj = 0; jj < 4; jj++) { wc[jj] = wb[jj*TWd]; wc[4+jj] = wb[jj*TWd + 128]; }
#pragma unroll 1
            for (int j = 0; j < TWd; j += 4) {
                if (j + 4 < TWd) {
                    const float* wp = wb + (j+4)*TWd;
#pragma unroll
                    for (int jj = 0; jj < 4; jj++) { wn[jj] = wp[jj*TWd]; wn[4+jj] = wp[jj*TWd + 128]; }
                }
                const ull pa0 = pack2(wc[0],wc[0]), pa1 = pack2(wc[1],wc[1]),
                          pa2 = pack2(wc[2],wc[2]), pa3 = pack2(wc[3],wc[3]);
                const ull pc0 = pack2(wc[4],wc[4]), pc1 = pack2(wc[5],wc[5]),
                          pc2 = pack2(wc[6],wc[6]), pc3 = pack2(wc[7],wc[7]);
#pragma unroll
                for (int k = 0; k < 9; k++) {
                    if (k < kc) {
                        ulonglong2 ha = *reinterpret_cast<const ulonglong2*>(buf + (kb+k)*512 + j*2);
                        ulonglong2 hb = *reinterpret_cast<const ulonglong2*>(buf + (kb+k)*512 + j*2 + 4);
                        fma2(acc0[k], ha.x, pa0); fma2(acc0[k], ha.y, pa1);
                        fma2(acc0[k], hb.x, pa2); fma2(acc0[k], hb.y, pa3);
                        fma2(acc1[k], ha.x, pc0); fma2(acc1[k], ha.y, pc1);
                        fma2(acc1[k], hb.x, pc2); fma2(acc1[k], hb.y, pc3);
                    }
                }
#pragma unroll
                for (int q = 0; q < 8; q++) wc[q] = wn[q];
            }
            __syncthreads();   // all warps done reading h0 rows [kb, kb+kc)
#pragma unroll
            for (int k = 0; k < 9; k++) {
                if (k < kc) {
                    float x0, x1; unpack2(acc0[k], x0, x1);
                    float y0, y1; unpack2(acc1[k], y0, y1);
                    *reinterpret_cast<ull*>(buf + (kb+k)*512 + 2*t) =
                        pack2(ftanh(x0+t1a), ftanh(x1+t1a));
                    *reinterpret_cast<ull*>(buf + (kb+k)*512 + 2*(t+128)) =
                        pack2(ftanh(y0+t1b), ftanh(y1+t1b));
                }
            }
        }
        __syncthreads();

        // ---- layer 2: k-split halves, 2 cols (tc, tc+64) per thread ----
        {
            ull accA[9], accB[9];
#pragma unroll
            for (int k = 0; k < 9; k++) { accA[k] = 0ull; accB[k] = 0ull; }
            const float* wbA = tw2 + tc;
            float wcA[4], wcB[4], wnA[4], wnB[4];
#pragma unroll
            for (int jj = 0; jj < 4; jj++) { wcA[jj] = wbA[jj*Ww]; wcB[jj] = wbA[jj*Ww + 64]; }
#pragma unroll 1
            for (int j = 0; j < TWd; j += 4) {
                if (j + 4 < TWd) {
                    const float* wp = wbA + (j+4)*Ww;
#pragma unroll
                    for (int jj = 0; jj < 4; jj++) { wnA[jj] = wp[jj*Ww]; wnB[jj] = wp[jj*Ww + 64]; }
                }
                const ull pA0 = pack2(wcA[0],wcA[0]), pA1 = pack2(wcA[1],wcA[1]),
                          pA2 = pack2(wcA[2],wcA[2]), pA3 = pack2(wcA[3],wcA[3]);
                const ull pB0 = pack2(wcB[0],wcB[0]), pB1 = pack2(wcB[1],wcB[1]),
                          pB2 = pack2(wcB[2],wcB[2]), pB3 = pack2(wcB[3],wcB[3]);
#pragma unroll
                for (int k = 0; k < 9; k++) {
                    if (k < kcs) {
                        ulonglong2 ha = *reinterpret_cast<const ulonglong2*>(buf + (kbs+k)*512 + j*2);
                        ulonglong2 hb = *reinterpret_cast<const ulonglong2*>(buf + (kbs+k)*512 + j*2 + 4);
                        fma2(accA[k], ha.x, pA0); fma2(accA[k], ha.y, pA1);
                        fma2(accA[k], hb.x, pA2); fma2(accA[k], hb.y, pA3);
                        fma2(accB[k], ha.x, pB0); fma2(accB[k], ha.y, pB1);
                        fma2(accB[k], hb.x, pB2); fma2(accB[k], hb.y, pB3);
                    }
                }
#pragma unroll
                for (int q = 0; q < 4; q++) { wcA[q] = wnA[q]; wcB[q] = wnB[q]; }
            }
            __syncthreads();   // all h1 reads done -> buf becomes [g | rr]
#pragma unroll
            for (int k = 0; k < 9; k++) {
                if (k < kcs) {
                    float x0, x1; unpack2(accA[k], x0, x1);
                    *reinterpret_cast<ull*>(buf + (kbs+k)*256 + 2*tc) =
                        pack2(__expf(ftanh(x0+tb2a)), __expf(ftanh(x1+tb2a)));
                    unpack2(accB[k], x0, x1);
                    *reinterpret_cast<ull*>(buf + (kbs+k)*256 + 2*(tc+64)) =
                        pack2(__expf(ftanh(x0+tb2b)), __expf(ftanh(x1+tb2b)));
                }
            }
            __syncthreads();
        }

        // ---- stage 1: rr[0]=res_v, rr[1+i]=res2[i] from old g rows 1..16 ----
        {
            ull r[K1];
#pragma unroll
            for (int k = 0; k < K1; k++) r[k] = 0ull;
#pragma unroll
            for (int j = 0; j < Kk; j++) {
                const ull g2 = *reinterpret_cast<const ull*>(buf + (1+j)*256 + 2*t);
#pragma unroll
                for (int k = 0; k < K1; k++)
                    fma2(r[k], g2, ws2[k*Kk + j]);
            }
#pragma unroll
            for (int k = 0; k < K1; k++)
                *reinterpret_cast<ull*>(buf + 4352 + k*256 + 2*t) = r[k];
            __syncthreads();
        }

        // ---- stage 2: g[k][c] += tanh(sw0T[:,c]@rr[k][:] + sb0[c]); k-split, 2 cols ----
        {
            ull sA[9], sB[9];
#pragma unroll
            for (int k = 0; k < 9; k++) { sA[k] = 0ull; sB[k] = 0ull; }
            const float* wb = d_sw0T + tc;
            float wcA[4], wcB[4], wnA[4], wnB[4];
#pragma unroll
            for (int ww = 0; ww < 4; ww++) { wcA[ww] = wb[ww*Ww]; wcB[ww] = wb[ww*Ww + 64]; }
#pragma unroll 1
            for (int w = 0; w < Ww; w += 4) {
                if (w + 4 < Ww) {
                    const float* wp = wb + (w+4)*Ww;
#pragma unroll
                    for (int ww = 0; ww < 4; ww++) { wnA[ww] = wp[ww*Ww]; wnB[ww] = wp[ww*Ww + 64]; }
                }
                const ull pA0 = pack2(wcA[0],wcA[0]), pA1 = pack2(wcA[1],wcA[1]),
                          pA2 = pack2(wcA[2],wcA[2]), pA3 = pack2(wcA[3],wcA[3]);
                const ull pB0 = pack2(wcB[0],wcB[0]), pB1 = pack2(wcB[1],wcB[1]),
                          pB2 = pack2(wcB[2],wcB[2]), pB3 = pack2(wcB[3],wcB[3]);
#pragma unroll
                for (int k = 0; k < 9; k++) {
                    if (k < kcs) {
                        ulonglong2 ra = *reinterpret_cast<const ulonglong2*>(buf + 4352 + (kbs+k)*256 + w*2);
                        ulonglong2 rb = *reinterpret_cast<const ulonglong2*>(buf + 4352 + (kbs+k)*256 + w*2 + 4);
                        fma2(sA[k], ra.x, pA0); fma2(sA[k], ra.y, pA1);
                        fma2(sA[k], rb.x, pA2); fma2(sA[k], rb.y, pA3);
                        fma2(sB[k], ra.x, pB0); fma2(sB[k], ra.y, pB1);
                        fma2(sB[k], rb.x, pB2); fma2(sB[k], rb.y, pB3);
                    }
                }
#pragma unroll
                for (int q = 0; q < 4; q++) { wcA[q] = wnA[q]; wcB[q] = wnB[q]; }
            }
#pragma unroll
            for (int k = 0; k < 9; k++) {
                if (k < kcs) {
                    float a0, a1; unpack2(sA[k], a0, a1);
                    ull* gp = reinterpret_cast<ull*>(buf + (kbs+k)*256 + 2*tc);
                    float g0, g1; unpack2(*gp, g0, g1);
                    *gp = pack2(g0 + ftanh(a0+sb0a), g1 + ftanh(a1+sb0a));
                    unpack2(sB[k], a0, a1);
                    gp = reinterpret_cast<ull*>(buf + (kbs+k)*256 + 2*(tc+64));
                    unpack2(*gp, g0, g1);
                    *gp = pack2(g0 + ftanh(a0+sb0b), g1 + ftanh(a1+sb0b));
                }
            }
            __syncthreads();
        }

        // ---- stage 3: resv2[t] = sum_k rw_v[k] * g'[1+k][t] ----
        {
            ull rv = 0ull;
#pragma unroll
            for (int k = 0; k < Kk; k++)
                fma2(rv, *reinterpret_cast<const ull*>(buf + (1+k)*256 + 2*t), ws2[k]);
            *reinterpret_cast<ull*>(sres + 2*t) = rv;
        }
        __syncthreads();

        // ---- stage 4: green = g'[0] + tanh(sw1T[:,t]@resv2 + sb1); gdot ----
        {
            ull sa = 0ull, sb = 0ull;
            const float* wb = d_sw1T + t;
#pragma unroll 1
            for (int w = 0; w < Ww; w += 4) {
                const float v0w = wb[(w+0)*Ww];
                const float v1w = wb[(w+1)*Ww];
                const float v2w = wb[(w+2)*Ww];
                const float v3w = wb[(w+3)*Ww];
                ulonglong2 ra = *reinterpret_cast<const ulonglong2*>(sres + w*2);
                ulonglong2 rb = *reinterpret_cast<const ulonglong2*>(sres + w*2 + 4);
                fma2(sa, ra.x, pack2(v0w,v0w)); fma2(sb, ra.y, pack2(v1w,v1w));
                fma2(sa, rb.x, pack2(v2w,v2w)); fma2(sb, rb.y, pack2(v3w,v3w));
            }
            const ull tot = add2(sa, sb);
            float a0, a1; unpack2(tot, a0, a1);
            float v0, v1; unpack2(*reinterpret_cast<const ull*>(buf + 2*t), v0, v1);
            float p0 = (v0 + ftanh(a0+sb1c)) * owc;
            float p1 = (v1 + ftanh(a1+sb1c)) * owc;
#pragma unroll
            for (int o = 16; o > 0; o >>= 1) {
                p0 += __shfl_down_sync(0xffffffffu, p0, o);
                p1 += __shfl_down_sync(0xffffffffu, p1, o);
            }
            if ((t & 31) == 0) { sred[(t>>5)*2] = p0; sred[(t>>5)*2+1] = p1; }
            __syncthreads();
            if (t == 0) {
                d_gdot[(b*Nn+n)*Mm + pair*2 + 0] = sred[0]+sred[2]+sred[4]+sred[6];
                d_gdot[(b*Nn+n)*Mm + pair*2 + 1] = sred[1]+sred[3]+sred[5]+sred[7];
            }
            __syncthreads();
        }
    }
}

// =====================================================================
__global__ void k6_final(const float* __restrict__ boundary,
                         const float* __restrict__ bweights,
                         float* __restrict__ out)
{
    __shared__ float s2[2];
    const int bn = blockIdx.x;
    const int b  = bn >> 5;
    const int t  = threadIdx.x;
    float v = d_gdot[bn*Mm + t] * boundary[b*Mm + t] * bweights[b*Mm + t];
#pragma unroll
    for (int o = 16; o > 0; o >>= 1) v += __shfl_down_sync(0xffffffffu, v, o);
    if ((t & 31) == 0) s2[t >> 5] = v;
    __syncthreads();
    if (t == 0) out[bn] = s2[0] + s2[1];
}

// =====================================================================
extern "C" void kernel_launch(void* const* d_in, const int* in_sizes, int n_in,
                              void* d_out, int out_size)
{
    const float* phase    = (const float*)d_in[0];
    const float* bcoords  = (const float*)d_in[1];
    const float* boundary = (const float*)d_in[2];
    const float* bweights = (const float*)d_in[3];
    const float* posc     = (const float*)d_in[4];
    const float* sigma    = (const float*)d_in[5];
    const float* velc     = (const float*)d_in[6];
    const float* vwt      = (const float*)d_in[7];
    const float* scat     = (const float*)d_in[8];
    const float* sscat    = (const float*)d_in[9];
    const float* aw0 = (const float*)d_in[10];
    const float* ab0 = (const float*)d_in[11];
    const float* aw1 = (const float*)d_in[12];
    const float* ab1 = (const float*)d_in[13];
    const float* aw2 = (const float*)d_in[14];
    const float* ab2 = (const float*)d_in[15];
    const float* tw0 = (const float*)d_in[16];
    const float* tb0 = (const float*)d_in[17];
    const float* tw1 = (const float*)d_in[18];
    const float* tb1 = (const float*)d_in[19];
    const float* tw2 = (const float*)d_in[20];
    const float* tb2 = (const float*)d_in[21];
    const float* sw0 = (const float*)d_in[22];
    const float* sb0 = (const float*)d_in[23];
    const float* sw1 = (const float*)d_in[24];
    const float* sb1 = (const float*)d_in[25];
    const float* ow  = (const float*)d_in[26];
    float* out = (float*)d_out;

    k_tr<<<64, 256>>>(sw0, sw1);
    k1_attn<<<Bb*Nn*K1, 128>>>(phase, posc, sigma, velc,
                               aw0, ab0, aw1, ab1, aw2, ab2, tw0, tb0);
    k_bm<<<Bb*Mm, TWd>>>(bcoords, tw0);
    k4_main<<<Bb*Nn*(Mm/4), 128>>>(
        scat, sscat, vwt, tw1, tb1, tw2, tb2, sb0, sb1, ow);
    k6_final<<<Bb*Nn, 64>>>(boundary, bweights, out);
}